// round 11
// baseline (speedup 1.0000x reference)
#include <cuda_runtime.h>
#include <cuda_fp16.h>
#include <cstdint>

// ---------------------------------------------------------------------------
// GCN 3-layer + mean-pool + MLP for GB300 (sm_103a) — Round 11
//  * dense_mma restructured for 2 blocks/SM (K chunks of 32, 18.9KB smem,
//    epilogue staged in two 64-row halves) — latency hiding across blocks
//  * agg16 gather unroll 4 -> 8 (MLP_eff on the random-gather path)
//  * factored normalization (h' = h*dinv), src-only 4B CSR payload,
//    rank-from-histogram build, lookback scan, fused layer-1, fp16 hidden
// Shape: N=50000, E=800000, D=3, H=128, G=64, H2=64, C=10
// ---------------------------------------------------------------------------

#define HDIM 128
#define MAXN 50176
#define MAXE 850000
#define MAXG 256

typedef int idx_t;

// Scratch
__device__ __half g_y16[MAXN * HDIM];   // GEMM input / agg output (zero past N)
__device__ __half g_h16[MAXN * HDIM];   // GEMM output, pre-scaled by dinv[row]
__device__ __half g_w2h[HDIM * HDIM];   // W2 in fp16
__device__ __half g_w3h[HDIM * HDIM];   // W3 in fp16
__device__ float4 g_pos4[MAXN];         // pos * dinv (xyz), w unused
__device__ float g_dinv[MAXN];
__device__ int   g_cnt[MAXN];
__device__ int   g_rank[MAXE];          // edge rank within its dst
__device__ int   g_off[MAXN];
__device__ int   g_csr_src[MAXE];       // src-only CSR payload
__device__ float g_gsum[MAXG * HDIM];
__device__ float g_gcnt[MAXG];
// decoupled-lookback state: hi 32 = flag (0/1/2), lo 32 = value; single 8B op.
__device__ unsigned long long g_state[64];

// --------------------------- PTX helpers (baseline ISA only) ----------------
__device__ __forceinline__ uint32_t smem_u32(const void* p) {
    uint32_t a;
    asm("{ .reg .u64 t; cvta.to.shared.u64 t, %1; cvt.u32.u64 %0, t; }"
        : "=r"(a) : "l"(p));
    return a;
}

__device__ __forceinline__ void ldsm_x4(uint32_t& r0, uint32_t& r1,
                                        uint32_t& r2, uint32_t& r3, uint32_t a) {
    asm volatile("ldmatrix.sync.aligned.m8n8.x4.shared.b16 {%0,%1,%2,%3}, [%4];"
                 : "=r"(r0), "=r"(r1), "=r"(r2), "=r"(r3) : "r"(a));
}

__device__ __forceinline__ void ldsm_x4_t(uint32_t& r0, uint32_t& r1,
                                          uint32_t& r2, uint32_t& r3, uint32_t a) {
    asm volatile("ldmatrix.sync.aligned.m8n8.x4.trans.shared.b16 {%0,%1,%2,%3}, [%4];"
                 : "=r"(r0), "=r"(r1), "=r"(r2), "=r"(r3) : "r"(a));
}

__device__ __forceinline__ void mma16816(float4& c, const uint32_t* a,
                                         uint32_t b0, uint32_t b1) {
    asm volatile("mma.sync.aligned.m16n8k16.row.col.f32.f16.f16.f32 "
                 "{%0,%1,%2,%3}, {%4,%5,%6,%7}, {%8,%9}, {%0,%1,%2,%3};"
                 : "+f"(c.x), "+f"(c.y), "+f"(c.z), "+f"(c.w)
                 : "r"(a[0]), "r"(a[1]), "r"(a[2]), "r"(a[3]),
                   "r"(b0), "r"(b1));
}

__device__ __forceinline__ void state_store(int b, unsigned long long v) {
    asm volatile("st.volatile.global.u64 [%0], %1;"
                 :: "l"(&g_state[b]), "l"(v) : "memory");
}

__device__ __forceinline__ unsigned long long state_load(int b) {
    unsigned long long v;
    asm volatile("ld.volatile.global.u64 %0, [%1];"
                 : "=l"(v) : "l"(&g_state[b]) : "memory");
    return v;
}

// ---------------------------------------------------------------------------
// setup + W2/W3 fp16 conversion (merged)
__global__ void setup_kernel(const float* __restrict__ W2,
                             const float* __restrict__ W3,
                             int N, int GH, int G) {
    int i = blockIdx.x * blockDim.x + threadIdx.x;
    if (i < N) g_cnt[i] = 0;
    if (i < GH) g_gsum[i] = 0.0f;
    if (i < G) g_gcnt[i] = 0.0f;
    if (i < 64) g_state[i] = 0ull;
    if (i < HDIM * HDIM) {
        g_w2h[i] = __float2half(W2[i]);
        g_w3h[i] = __float2half(W3[i]);
    }
}

// Histogram + edge rank (atomicAdd's return value = unique slot within dst)
__global__ void hist_kernel(const idx_t* __restrict__ ei, int E, int N) {
    int e = blockIdx.x * blockDim.x + threadIdx.x;
    if (e >= E) return;
    int d = (int)ei[(long long)E + e];
    int r = 0;
    if ((unsigned)d < (unsigned)N) r = atomicAdd(&g_cnt[d], 1);
    g_rank[e] = r;
}

// --- single-pass decoupled-lookback scan; also emits dinv and pos*dinv ------
#define SCAN_T 4
#define SCAN_THREADS 256
#define SCAN_CHUNK (SCAN_THREADS * SCAN_T)

__global__ void __launch_bounds__(SCAN_THREADS)
scan_kernel(const float* __restrict__ pos, int N) {
    __shared__ int warp_sums[8];
    __shared__ int s_base;
    int b = blockIdx.x, t = threadIdx.x;
    int base = b * SCAN_CHUNK + t * SCAN_T;

    int v[SCAN_T];
    int sum = 0;
#pragma unroll
    for (int i = 0; i < SCAN_T; i++) {
        int idx = base + i;
        v[i] = (idx < N) ? g_cnt[idx] : 0;
        sum += v[i];
    }
    int lane = t & 31, wid = t >> 5;
    int x = sum;
#pragma unroll
    for (int o = 1; o < 32; o <<= 1) {
        int y = __shfl_up_sync(0xFFFFFFFFu, x, o);
        if (lane >= o) x += y;
    }
    if (lane == 31) warp_sums[wid] = x;
    __syncthreads();
    if (wid == 0 && lane < 8) {
        int y = warp_sums[lane];
#pragma unroll
        for (int o = 1; o < 8; o <<= 1) {
            int z = __shfl_up_sync(0xFFu, y, o);
            if (lane >= o) y += z;
        }
        warp_sums[lane] = y;
    }
    __syncthreads();
    int thread_excl = x - sum + (wid > 0 ? warp_sums[wid - 1] : 0);
    int block_total = warp_sums[7];

    if (t == 0) {
        if (b == 0) {
            s_base = 0;
            state_store(0, (2ull << 32) | (unsigned)block_total);
        } else {
            state_store(b, (1ull << 32) | (unsigned)block_total);
            int excl = 0;
            for (int j = b - 1; j >= 0;) {
                unsigned long long st;
                do { st = state_load(j); } while ((st >> 32) == 0);
                excl += (int)(unsigned)st;
                if ((st >> 32) == 2ull) break;
                j--;
            }
            s_base = excl;
            state_store(b, (2ull << 32) | (unsigned)(excl + block_total));
        }
    }
    __syncthreads();

    int off = s_base + thread_excl;
#pragma unroll
    for (int i = 0; i < SCAN_T; i++) {
        int idx = base + i;
        if (idx < N) {
            g_off[idx] = off;
            off += v[i];
            float di = rsqrtf((float)(v[i] + 1));
            g_dinv[idx] = di;
            g_pos4[idx] = make_float4(pos[idx * 3 + 0] * di,
                                      pos[idx * 3 + 1] * di,
                                      pos[idx * 3 + 2] * di, 0.f);
        }
    }
}

// CSR fill: slot = off[d] + rank; one 4B scattered store, no dinv gathers.
__global__ void edge_fill(const idx_t* __restrict__ ei, int E, int N) {
    int e = blockIdx.x * blockDim.x + threadIdx.x;
    if (e >= E) return;
    int s = (int)ei[e];
    int d = (int)ei[(long long)E + e];
    if ((unsigned)s >= (unsigned)N || (unsigned)d >= (unsigned)N) return;
    int p = g_off[d] + g_rank[e];
    if (p < MAXE) g_csr_src[p] = s;
}

// --- Fused layer 1: pos'-space aggregation + dense + relu -> fp16 -----------
__global__ void __launch_bounds__(256)
layer1_kernel(const float* __restrict__ W1,
              const float* __restrict__ b1, int N) {
    int n = blockIdx.x * 8 + (threadIdx.x >> 5);
    if (n >= N) return;
    int lane = threadIdx.x & 31;

    float a0 = 0.f, a1 = 0.f, a2 = 0.f;
    int e0 = g_off[n], end = e0 + g_cnt[n];
    for (int e = e0 + lane; e < end; e += 32) {
        float4 p = g_pos4[g_csr_src[e]];
        a0 += p.x; a1 += p.y; a2 += p.z;
    }
#pragma unroll
    for (int o = 16; o > 0; o >>= 1) {
        a0 += __shfl_down_sync(0xFFFFFFFFu, a0, o);
        a1 += __shfl_down_sync(0xFFFFFFFFu, a1, o);
        a2 += __shfl_down_sync(0xFFFFFFFFu, a2, o);
    }
    float di = g_dinv[n];
    float4 ps = g_pos4[n];
    float x0 = (__shfl_sync(0xFFFFFFFFu, a0, 0) + ps.x) * di;
    float x1 = (__shfl_sync(0xFFFFFFFFu, a1, 0) + ps.y) * di;
    float x2 = (__shfl_sync(0xFFFFFFFFu, a2, 0) + ps.z) * di;

    int q = lane;
    float4 w0 = *(const float4*)&W1[0 * HDIM + q * 4];
    float4 w1 = *(const float4*)&W1[1 * HDIM + q * 4];
    float4 w2 = *(const float4*)&W1[2 * HDIM + q * 4];
    float4 b4 = *(const float4*)&b1[q * 4];
    float4 a;
    a.x = fmaxf(b4.x + x0 * w0.x + x1 * w1.x + x2 * w2.x, 0.f);
    a.y = fmaxf(b4.y + x0 * w0.y + x1 * w1.y + x2 * w2.y, 0.f);
    a.z = fmaxf(b4.z + x0 * w0.z + x1 * w1.z + x2 * w2.z, 0.f);
    a.w = fmaxf(b4.w + x0 * w0.w + x1 * w1.w + x2 * w2.w, 0.f);
    __half2 h01 = __floats2half2_rn(a.x, a.y);
    __half2 h23 = __floats2half2_rn(a.z, a.w);
    *(uint2*)&g_y16[(size_t)n * HDIM + q * 4] =
        make_uint2(*(uint32_t*)&h01, *(uint32_t*)&h23);
}

// --- Dense layers 2/3 via HMMA, 2 blocks/SM ----------------------------------
// K in 4 chunks of 32; smem = As(128x40) + Bs(32x136) = 18.9KB;
// epilogue staged in two 64-row halves (Cs reuses the same buffer).
#define AS_STRIDE 40    // halves per A row (32 + 8 pad)
#define BS_STRIDE 136   // halves per B row (128 + 8 pad)
#define CS_STRIDE 136

__global__ void __launch_bounds__(256, 2)
dense_mma_kernel(int layer, int N) {
    const __half* __restrict__ Wh = (layer == 2) ? g_w2h : g_w3h;

    __shared__ __align__(16) char smraw[(128 * AS_STRIDE + 32 * BS_STRIDE) * 2];
    __half* As = (__half*)smraw;                     // 128 x 40
    __half* Bs = As + 128 * AS_STRIDE;               // 32 x 136
    __half* Cs = (__half*)smraw;                     // 64 x 136 (reuse, 17.4KB)

    int tid = threadIdx.x;
    int wid = tid >> 5;
    int lane = tid & 31;
    int nb = blockIdx.x * 128;

    int m0 = (wid & 3) * 32;
    int n0 = (wid >> 2) * 64;

    float4 acc[2][8];
#pragma unroll
    for (int i = 0; i < 2; i++)
#pragma unroll
        for (int j = 0; j < 8; j++) acc[i][j] = make_float4(0.f, 0.f, 0.f, 0.f);

#pragma unroll
    for (int c = 0; c < 4; c++) {
        __syncthreads();
        // A chunk: 128 rows x 32 halves = 512 uint4; 2 per thread
#pragma unroll
        for (int t = 0; t < 2; t++) {
            int i = tid + t * 256;
            int row = i >> 2, q = i & 3;
            uint4 v = *(const uint4*)&g_y16[(size_t)(nb + row) * HDIM + c * 32 + q * 8];
            *(uint4*)&As[row * AS_STRIDE + q * 8] = v;
        }
        // B chunk: 32 rows x 128 halves = 512 uint4; 2 per thread
#pragma unroll
        for (int t = 0; t < 2; t++) {
            int i = tid + t * 256;
            int row = i >> 4, q = i & 15;
            uint4 v = *(const uint4*)&Wh[(size_t)(c * 32 + row) * HDIM + q * 8];
            *(uint4*)&Bs[row * BS_STRIDE + q * 8] = v;
        }
        __syncthreads();

#pragma unroll
        for (int kk = 0; kk < 2; kk++) {
            int k16 = kk * 16;
            uint32_t af[2][4];
#pragma unroll
            for (int mt = 0; mt < 2; mt++) {
                uint32_t a = smem_u32(
                    &As[(m0 + mt * 16 + (lane & 15)) * AS_STRIDE + k16 + (lane >> 4) * 8]);
                ldsm_x4(af[mt][0], af[mt][1], af[mt][2], af[mt][3], a);
            }
            uint32_t bf[8][2];
#pragma unroll
            for (int nt2 = 0; nt2 < 4; nt2++) {
                uint32_t a = smem_u32(
                    &Bs[(k16 + (lane & 15)) * BS_STRIDE + n0 + nt2 * 16 + (lane >> 4) * 8]);
                uint32_t r0, r1, r2, r3;
                ldsm_x4_t(r0, r1, r2, r3, a);
                bf[nt2 * 2 + 0][0] = r0; bf[nt2 * 2 + 0][1] = r1;
                bf[nt2 * 2 + 1][0] = r2; bf[nt2 * 2 + 1][1] = r3;
            }
#pragma unroll
            for (int mt = 0; mt < 2; mt++)
#pragma unroll
                for (int nt = 0; nt < 8; nt++)
                    mma16816(acc[mt][nt], af[mt], bf[nt][0], bf[nt][1]);
        }
    }

    // Epilogue in two 64-row passes: scale by dinv, fp16 -> smem, coalesced.
    int tg = lane >> 2, tp = lane & 3;
#pragma unroll
    for (int p = 0; p < 2; p++) {
        __syncthreads();
        if (((wid & 3) >> 1) == p) {
            int mloc = m0 - p * 64;          // 0 or 32 within this pass
#pragma unroll
            for (int mt = 0; mt < 2; mt++) {
                int rl = mloc + mt * 16 + tg;            // local row 0..63
                int rg = nb + p * 64 + mloc + mt * 16 + tg;
                float dA = g_dinv[rg];
                float dB = g_dinv[rg + 8];
#pragma unroll
                for (int nt = 0; nt < 8; nt++) {
                    int col = n0 + nt * 8 + 2 * tp;
                    __half2 hA = __floats2half2_rn(acc[mt][nt].x * dA,
                                                   acc[mt][nt].y * dA);
                    __half2 hB = __floats2half2_rn(acc[mt][nt].z * dB,
                                                   acc[mt][nt].w * dB);
                    *(__half2*)&Cs[rl * CS_STRIDE + col] = hA;
                    *(__half2*)&Cs[(rl + 8) * CS_STRIDE + col] = hB;
                }
            }
        }
        __syncthreads();
        // 64 rows x 16 uint4 = 1024 units; 4 per thread
#pragma unroll
        for (int t = 0; t < 4; t++) {
            int i = tid + t * 256;
            int row = i >> 4, q = i & 15;
            int node = nb + p * 64 + row;
            if (node < N) {
                uint4 v = *(const uint4*)&Cs[row * CS_STRIDE + q * 8];
                *(uint4*)&g_h16[(size_t)node * HDIM + q * 8] = v;
            }
        }
    }
}

// --- CSR aggregation: y[d] = relu(b + dinv[d]*(h'[d] + sum h'[src])) --------
// 8-edge unrolled gather (8 independent loads in flight).
__global__ void __launch_bounds__(256)
agg16_kernel(const float* __restrict__ b, int N, int mode,
             const idx_t* __restrict__ batch, int G) {
    int n = blockIdx.x * 8 + (threadIdx.x >> 5);
    if (n >= N) return;
    int lane = threadIdx.x & 31;

    float4 acc = make_float4(0.f, 0.f, 0.f, 0.f);
    int e = g_off[n];
    int end = e + g_cnt[n];
    for (; e + 7 < end; e += 8) {
        int s0 = g_csr_src[e],     s1 = g_csr_src[e + 1];
        int s2 = g_csr_src[e + 2], s3 = g_csr_src[e + 3];
        int s4 = g_csr_src[e + 4], s5 = g_csr_src[e + 5];
        int s6 = g_csr_src[e + 6], s7 = g_csr_src[e + 7];
        uint2 u0 = *(const uint2*)&g_h16[(size_t)s0 * HDIM + lane * 4];
        uint2 u1 = *(const uint2*)&g_h16[(size_t)s1 * HDIM + lane * 4];
        uint2 u2 = *(const uint2*)&g_h16[(size_t)s2 * HDIM + lane * 4];
        uint2 u3 = *(const uint2*)&g_h16[(size_t)s3 * HDIM + lane * 4];
        uint2 u4 = *(const uint2*)&g_h16[(size_t)s4 * HDIM + lane * 4];
        uint2 u5 = *(const uint2*)&g_h16[(size_t)s5 * HDIM + lane * 4];
        uint2 u6 = *(const uint2*)&g_h16[(size_t)s6 * HDIM + lane * 4];
        uint2 u7 = *(const uint2*)&g_h16[(size_t)s7 * HDIM + lane * 4];
        float2 p0 = __half22float2(*(__half2*)&u0.x);
        float2 q0 = __half22float2(*(__half2*)&u0.y);
        float2 p1 = __half22float2(*(__half2*)&u1.x);
        float2 q1 = __half22float2(*(__half2*)&u1.y);
        float2 p2 = __half22float2(*(__half2*)&u2.x);
        float2 q2 = __half22float2(*(__half2*)&u2.y);
        float2 p3 = __half22float2(*(__half2*)&u3.x);
        float2 q3 = __half22float2(*(__half2*)&u3.y);
        float2 p4 = __half22float2(*(__half2*)&u4.x);
        float2 q4 = __half22float2(*(__half2*)&u4.y);
        float2 p5 = __half22float2(*(__half2*)&u5.x);
        float2 q5 = __half22float2(*(__half2*)&u5.y);
        float2 p6 = __half22float2(*(__half2*)&u6.x);
        float2 q6 = __half22float2(*(__half2*)&u6.y);
        float2 p7 = __half22float2(*(__half2*)&u7.x);
        float2 q7 = __half22float2(*(__half2*)&u7.y);
        acc.x += ((p0.x + p1.x) + (p2.x + p3.x)) + ((p4.x + p5.x) + (p6.x + p7.x));
        acc.y += ((p0.y + p1.y) + (p2.y + p3.y)) + ((p4.y + p5.y) + (p6.y + p7.y));
        acc.z += ((q0.x + q1.x) + (q2.x + q3.x)) + ((q4.x + q5.x) + (q6.x + q7.x));
        acc.w += ((q0.y + q1.y) + (q2.y + q3.y)) + ((q4.y + q5.y) + (q6.y + q7.y));
    }
    for (; e + 1 < end; e += 2) {
        int s0 = g_csr_src[e], s1 = g_csr_src[e + 1];
        uint2 u0 = *(const uint2*)&g_h16[(size_t)s0 * HDIM + lane * 4];
        uint2 u1 = *(const uint2*)&g_h16[(size_t)s1 * HDIM + lane * 4];
        float2 p0 = __half22float2(*(__half2*)&u0.x);
        float2 q0 = __half22float2(*(__half2*)&u0.y);
        float2 p1 = __half22float2(*(__half2*)&u1.x);
        float2 q1 = __half22float2(*(__half2*)&u1.y);
        acc.x += p0.x + p1.x; acc.y += p0.y + p1.y;
        acc.z += q0.x + q1.x; acc.w += q0.y + q1.y;
    }
    if (e < end) {
        int s0 = g_csr_src[e];
        uint2 u0 = *(const uint2*)&g_h16[(size_t)s0 * HDIM + lane * 4];
        float2 p0 = __half22float2(*(__half2*)&u0.x);
        float2 q0 = __half22float2(*(__half2*)&u0.y);
        acc.x += p0.x; acc.y += p0.y;
        acc.z += q0.x; acc.w += q0.y;
    }

    // Self term + bias + normalization + relu
    float di = g_dinv[n];
    float4 b4 = *(const float4*)&b[lane * 4];
    uint2 hs = *(const uint2*)&g_h16[(size_t)n * HDIM + lane * 4];
    float2 f0 = __half22float2(*(__half2*)&hs.x);
    float2 f1 = __half22float2(*(__half2*)&hs.y);
    acc.x = fmaxf(b4.x + di * (acc.x + f0.x), 0.f);
    acc.y = fmaxf(b4.y + di * (acc.y + f0.y), 0.f);
    acc.z = fmaxf(b4.z + di * (acc.z + f1.x), 0.f);
    acc.w = fmaxf(b4.w + di * (acc.w + f1.y), 0.f);

    if (mode == 0) {
        __half2 h01 = __floats2half2_rn(acc.x, acc.y);
        __half2 h23 = __floats2half2_rn(acc.z, acc.w);
        *(uint2*)&g_y16[(size_t)n * HDIM + lane * 4] =
            make_uint2(*(uint32_t*)&h01, *(uint32_t*)&h23);
    } else {
        int bg = (int)__ldg(&batch[n]);
        if ((unsigned)bg < (unsigned)G) {
            float* p = &g_gsum[bg * HDIM + lane * 4];
            asm volatile("red.global.add.v4.f32 [%0], {%1,%2,%3,%4};"
                         :: "l"(p), "f"(acc.x), "f"(acc.y), "f"(acc.z), "f"(acc.w)
                         : "memory");
            if (lane == 0) atomicAdd(&g_gcnt[bg], 1.0f);
        }
    }
}

// --- Final MLP: one block per graph ------------------------------------------
__global__ void __launch_bounds__(128)
mlp_kernel(const float* __restrict__ Wl1,
           const float* __restrict__ bl1,
           const float* __restrict__ Wl2,
           const float* __restrict__ bl2,
           float* __restrict__ out,
           int H2, int C) {
    __shared__ float xs[HDIM];
    __shared__ float h1[64];
    int g = blockIdx.x;
    int tid = threadIdx.x;

    float inv = 1.0f / fmaxf(g_gcnt[g], 1.0f);
    if (tid < HDIM) xs[tid] = g_gsum[g * HDIM + tid] * inv;
    __syncthreads();

    if (tid < H2) {
        float s = bl1[tid];
        for (int k = 0; k < HDIM; k++)
            s += xs[k] * Wl1[k * H2 + tid];
        h1[tid] = fmaxf(s, 0.f);
    }
    __syncthreads();

    if (tid < C) {
        float s = bl2[tid];
        for (int j = 0; j < H2; j++)
            s += h1[j] * Wl2[j * C + tid];
        out[g * C + tid] = s;
    }
}

// ---------------------------------------------------------------------------
extern "C" void kernel_launch(void* const* d_in, const int* in_sizes, int n_in,
                              void* d_out, int out_size) {
    const float* pos  = (const float*)d_in[0];
    const idx_t* ei   = (const idx_t*)d_in[1];
    const idx_t* batch= (const idx_t*)d_in[2];
    const float* W1   = (const float*)d_in[3];
    const float* b1   = (const float*)d_in[4];
    const float* W2   = (const float*)d_in[5];
    const float* b2   = (const float*)d_in[6];
    const float* W3   = (const float*)d_in[7];
    const float* b3   = (const float*)d_in[8];
    const float* Wl1  = (const float*)d_in[9];
    const float* bl1  = (const float*)d_in[10];
    const float* Wl2  = (const float*)d_in[11];
    const float* bl2  = (const float*)d_in[12];
    float* out = (float*)d_out;

    int H  = in_sizes[4];              // 128
    int D  = in_sizes[3] / H;          // 3
    int N  = in_sizes[0] / D;          // 50000
    int E  = in_sizes[1] / 2;          // 800000
    int H2 = in_sizes[10];             // 64
    int C  = in_sizes[12];             // 10
    int G  = out_size / C;             // 64

    int initN = N > G * H ? N : G * H;
    setup_kernel<<<(initN + 255) / 256, 256>>>(W2, W3, N, G * H, G);
    hist_kernel<<<(E + 255) / 256, 256>>>(ei, E, N);
    scan_kernel<<<(N + SCAN_CHUNK - 1) / SCAN_CHUNK, SCAN_THREADS>>>(pos, N);
    edge_fill<<<(E + 255) / 256, 256>>>(ei, E, N);

    // Layer 1 (fused: pos'-space aggregation + dense + relu)
    layer1_kernel<<<(N + 7) / 8, 256>>>(W1, b1, N);

    // Layer 2
    dense_mma_kernel<<<(N + 127) / 128, 256>>>(2, N);
    agg16_kernel<<<(N + 7) / 8, 256>>>(b2, N, 0, batch, G);

    // Layer 3 (aggregation fused with mean-pool)
    dense_mma_kernel<<<(N + 127) / 128, 256>>>(3, N);
    agg16_kernel<<<(N + 7) / 8, 256>>>(b3, N, 1, batch, G);

    mlp_kernel<<<G, 128>>>(Wl1, bl1, Wl2, bl2, out, H2, C);
}

// round 12
// speedup vs baseline: 1.0154x; 1.0154x over previous
#include <cuda_runtime.h>
#include <cuda_fp16.h>
#include <cstdint>

// ---------------------------------------------------------------------------
// GCN 3-layer + mean-pool + MLP for GB300 (sm_103a) — Round 12
//  * REVERT round-11 (regressed): agg back to 4-edge unroll; dense K=64 chunks
//  * dense_mma: 64-row M-blocks, warp tile 32x32, 26.6KB smem, lb(256,3)
//    -> ~3 blocks/SM for cross-block latency hiding (round-11 tried this via
//       smaller K chunks and lost to extra syncs; this keeps sync count)
//  * factored normalization (h'=h*dinv), src-only CSR, rank-from-histogram,
//    lookback scan, fused layer-1, fp16 hidden, fused mean-pool
// Shape: N=50000, E=800000, D=3, H=128, G=64, H2=64, C=10
// ---------------------------------------------------------------------------

#define HDIM 128
#define MAXN 50176
#define MAXE 850000
#define MAXG 256

typedef int idx_t;

// Scratch
__device__ __half g_y16[MAXN * HDIM];   // GEMM input / agg output (zero past N)
__device__ __half g_h16[MAXN * HDIM];   // GEMM output, pre-scaled by dinv[row]
__device__ __half g_w2h[HDIM * HDIM];   // W2 in fp16
__device__ __half g_w3h[HDIM * HDIM];   // W3 in fp16
__device__ float4 g_pos4[MAXN];         // pos * dinv (xyz), w unused
__device__ float g_dinv[MAXN];
__device__ int   g_cnt[MAXN];
__device__ int   g_rank[MAXE];          // edge rank within its dst
__device__ int   g_off[MAXN];
__device__ int   g_csr_src[MAXE];       // src-only CSR payload
__device__ float g_gsum[MAXG * HDIM];
__device__ float g_gcnt[MAXG];
// decoupled-lookback state: hi 32 = flag (0/1/2), lo 32 = value; single 8B op.
__device__ unsigned long long g_state[64];

// --------------------------- PTX helpers (baseline ISA only) ----------------
__device__ __forceinline__ uint32_t smem_u32(const void* p) {
    uint32_t a;
    asm("{ .reg .u64 t; cvta.to.shared.u64 t, %1; cvt.u32.u64 %0, t; }"
        : "=r"(a) : "l"(p));
    return a;
}

__device__ __forceinline__ void ldsm_x4(uint32_t& r0, uint32_t& r1,
                                        uint32_t& r2, uint32_t& r3, uint32_t a) {
    asm volatile("ldmatrix.sync.aligned.m8n8.x4.shared.b16 {%0,%1,%2,%3}, [%4];"
                 : "=r"(r0), "=r"(r1), "=r"(r2), "=r"(r3) : "r"(a));
}

__device__ __forceinline__ void ldsm_x4_t(uint32_t& r0, uint32_t& r1,
                                          uint32_t& r2, uint32_t& r3, uint32_t a) {
    asm volatile("ldmatrix.sync.aligned.m8n8.x4.trans.shared.b16 {%0,%1,%2,%3}, [%4];"
                 : "=r"(r0), "=r"(r1), "=r"(r2), "=r"(r3) : "r"(a));
}

__device__ __forceinline__ void mma16816(float4& c, const uint32_t* a,
                                         uint32_t b0, uint32_t b1) {
    asm volatile("mma.sync.aligned.m16n8k16.row.col.f32.f16.f16.f32 "
                 "{%0,%1,%2,%3}, {%4,%5,%6,%7}, {%8,%9}, {%0,%1,%2,%3};"
                 : "+f"(c.x), "+f"(c.y), "+f"(c.z), "+f"(c.w)
                 : "r"(a[0]), "r"(a[1]), "r"(a[2]), "r"(a[3]),
                   "r"(b0), "r"(b1));
}

__device__ __forceinline__ void state_store(int b, unsigned long long v) {
    asm volatile("st.volatile.global.u64 [%0], %1;"
                 :: "l"(&g_state[b]), "l"(v) : "memory");
}

__device__ __forceinline__ unsigned long long state_load(int b) {
    unsigned long long v;
    asm volatile("ld.volatile.global.u64 %0, [%1];"
                 : "=l"(v) : "l"(&g_state[b]) : "memory");
    return v;
}

// ---------------------------------------------------------------------------
// setup + W2/W3 fp16 conversion (merged)
__global__ void setup_kernel(const float* __restrict__ W2,
                             const float* __restrict__ W3,
                             int N, int GH, int G) {
    int i = blockIdx.x * blockDim.x + threadIdx.x;
    if (i < N) g_cnt[i] = 0;
    if (i < GH) g_gsum[i] = 0.0f;
    if (i < G) g_gcnt[i] = 0.0f;
    if (i < 64) g_state[i] = 0ull;
    if (i < HDIM * HDIM) {
        g_w2h[i] = __float2half(W2[i]);
        g_w3h[i] = __float2half(W3[i]);
    }
}

// Histogram + edge rank (atomicAdd's return value = unique slot within dst)
__global__ void hist_kernel(const idx_t* __restrict__ ei, int E, int N) {
    int e = blockIdx.x * blockDim.x + threadIdx.x;
    if (e >= E) return;
    int d = (int)ei[(long long)E + e];
    int r = 0;
    if ((unsigned)d < (unsigned)N) r = atomicAdd(&g_cnt[d], 1);
    g_rank[e] = r;
}

// --- single-pass decoupled-lookback scan; also emits dinv and pos*dinv ------
#define SCAN_T 4
#define SCAN_THREADS 256
#define SCAN_CHUNK (SCAN_THREADS * SCAN_T)

__global__ void __launch_bounds__(SCAN_THREADS)
scan_kernel(const float* __restrict__ pos, int N) {
    __shared__ int warp_sums[8];
    __shared__ int s_base;
    int b = blockIdx.x, t = threadIdx.x;
    int base = b * SCAN_CHUNK + t * SCAN_T;

    int v[SCAN_T];
    int sum = 0;
#pragma unroll
    for (int i = 0; i < SCAN_T; i++) {
        int idx = base + i;
        v[i] = (idx < N) ? g_cnt[idx] : 0;
        sum += v[i];
    }
    int lane = t & 31, wid = t >> 5;
    int x = sum;
#pragma unroll
    for (int o = 1; o < 32; o <<= 1) {
        int y = __shfl_up_sync(0xFFFFFFFFu, x, o);
        if (lane >= o) x += y;
    }
    if (lane == 31) warp_sums[wid] = x;
    __syncthreads();
    if (wid == 0 && lane < 8) {
        int y = warp_sums[lane];
#pragma unroll
        for (int o = 1; o < 8; o <<= 1) {
            int z = __shfl_up_sync(0xFFu, y, o);
            if (lane >= o) y += z;
        }
        warp_sums[lane] = y;
    }
    __syncthreads();
    int thread_excl = x - sum + (wid > 0 ? warp_sums[wid - 1] : 0);
    int block_total = warp_sums[7];

    if (t == 0) {
        if (b == 0) {
            s_base = 0;
            state_store(0, (2ull << 32) | (unsigned)block_total);
        } else {
            state_store(b, (1ull << 32) | (unsigned)block_total);
            int excl = 0;
            for (int j = b - 1; j >= 0;) {
                unsigned long long st;
                do { st = state_load(j); } while ((st >> 32) == 0);
                excl += (int)(unsigned)st;
                if ((st >> 32) == 2ull) break;
                j--;
            }
            s_base = excl;
            state_store(b, (2ull << 32) | (unsigned)(excl + block_total));
        }
    }
    __syncthreads();

    int off = s_base + thread_excl;
#pragma unroll
    for (int i = 0; i < SCAN_T; i++) {
        int idx = base + i;
        if (idx < N) {
            g_off[idx] = off;
            off += v[i];
            float di = rsqrtf((float)(v[i] + 1));
            g_dinv[idx] = di;
            g_pos4[idx] = make_float4(pos[idx * 3 + 0] * di,
                                      pos[idx * 3 + 1] * di,
                                      pos[idx * 3 + 2] * di, 0.f);
        }
    }
}

// CSR fill: slot = off[d] + rank; one 4B scattered store, no dinv gathers.
__global__ void edge_fill(const idx_t* __restrict__ ei, int E, int N) {
    int e = blockIdx.x * blockDim.x + threadIdx.x;
    if (e >= E) return;
    int s = (int)ei[e];
    int d = (int)ei[(long long)E + e];
    if ((unsigned)s >= (unsigned)N || (unsigned)d >= (unsigned)N) return;
    int p = g_off[d] + g_rank[e];
    if (p < MAXE) g_csr_src[p] = s;
}

// --- Fused layer 1: pos'-space aggregation + dense + relu -> fp16 -----------
__global__ void __launch_bounds__(256)
layer1_kernel(const float* __restrict__ W1,
              const float* __restrict__ b1, int N) {
    int n = blockIdx.x * 8 + (threadIdx.x >> 5);
    if (n >= N) return;
    int lane = threadIdx.x & 31;

    float a0 = 0.f, a1 = 0.f, a2 = 0.f;
    int e0 = g_off[n], end = e0 + g_cnt[n];
    for (int e = e0 + lane; e < end; e += 32) {
        float4 p = g_pos4[g_csr_src[e]];
        a0 += p.x; a1 += p.y; a2 += p.z;
    }
#pragma unroll
    for (int o = 16; o > 0; o >>= 1) {
        a0 += __shfl_down_sync(0xFFFFFFFFu, a0, o);
        a1 += __shfl_down_sync(0xFFFFFFFFu, a1, o);
        a2 += __shfl_down_sync(0xFFFFFFFFu, a2, o);
    }
    float di = g_dinv[n];
    float4 ps = g_pos4[n];
    float x0 = (__shfl_sync(0xFFFFFFFFu, a0, 0) + ps.x) * di;
    float x1 = (__shfl_sync(0xFFFFFFFFu, a1, 0) + ps.y) * di;
    float x2 = (__shfl_sync(0xFFFFFFFFu, a2, 0) + ps.z) * di;

    int q = lane;
    float4 w0 = *(const float4*)&W1[0 * HDIM + q * 4];
    float4 w1 = *(const float4*)&W1[1 * HDIM + q * 4];
    float4 w2 = *(const float4*)&W1[2 * HDIM + q * 4];
    float4 b4 = *(const float4*)&b1[q * 4];
    float4 a;
    a.x = fmaxf(b4.x + x0 * w0.x + x1 * w1.x + x2 * w2.x, 0.f);
    a.y = fmaxf(b4.y + x0 * w0.y + x1 * w1.y + x2 * w2.y, 0.f);
    a.z = fmaxf(b4.z + x0 * w0.z + x1 * w1.z + x2 * w2.z, 0.f);
    a.w = fmaxf(b4.w + x0 * w0.w + x1 * w1.w + x2 * w2.w, 0.f);
    __half2 h01 = __floats2half2_rn(a.x, a.y);
    __half2 h23 = __floats2half2_rn(a.z, a.w);
    *(uint2*)&g_y16[(size_t)n * HDIM + q * 4] =
        make_uint2(*(uint32_t*)&h01, *(uint32_t*)&h23);
}

// --- Dense layers 2/3 via HMMA: 64-row blocks, warp tile 32x32 ---------------
// K in 2 chunks of 64; smem = As(64x72) + Bs(64x136) = 26.6KB -> ~3 blocks/SM.
#define AS_STRIDE 72    // halves per A row (64 + 8 pad)
#define BS_STRIDE 136   // halves per B row (128 + 8 pad)
#define CS_STRIDE 136

__global__ void __launch_bounds__(256, 3)
dense_mma_kernel(int layer, int N) {
    const __half* __restrict__ Wh = (layer == 2) ? g_w2h : g_w3h;

    __shared__ __align__(16) char smraw[(64 * AS_STRIDE + 64 * BS_STRIDE) * 2];
    __half* As = (__half*)smraw;                     // 64 x 72
    __half* Bs = As + 64 * AS_STRIDE;                // 64 x 136
    __half* Cs = (__half*)smraw;                     // 64 x 136 (reuse)

    int tid = threadIdx.x;
    int wid = tid >> 5;
    int lane = tid & 31;
    int nb = blockIdx.x * 64;

    int m0 = (wid & 1) * 32;     // warp m offset (2 tiles of 32)
    int n0 = (wid >> 1) * 32;    // warp n offset (4 tiles of 32)

    float4 acc[2][4];
#pragma unroll
    for (int i = 0; i < 2; i++)
#pragma unroll
        for (int j = 0; j < 4; j++) acc[i][j] = make_float4(0.f, 0.f, 0.f, 0.f);

#pragma unroll
    for (int c = 0; c < 2; c++) {
        __syncthreads();
        // A chunk: 64 rows x 64 halves = 512 uint4; 2 per thread
#pragma unroll
        for (int t = 0; t < 2; t++) {
            int i = tid + t * 256;
            int row = i >> 3, q = i & 7;
            uint4 v = *(const uint4*)&g_y16[(size_t)(nb + row) * HDIM + c * 64 + q * 8];
            *(uint4*)&As[row * AS_STRIDE + q * 8] = v;
        }
        // B chunk: rows c*64..+63 x 128 halves = 1024 uint4; 4 per thread
#pragma unroll
        for (int t = 0; t < 4; t++) {
            int i = tid + t * 256;
            int row = i >> 4, q = i & 15;
            uint4 v = *(const uint4*)&Wh[(size_t)(c * 64 + row) * HDIM + q * 8];
            *(uint4*)&Bs[row * BS_STRIDE + q * 8] = v;
        }
        __syncthreads();

#pragma unroll
        for (int kk = 0; kk < 4; kk++) {
            int k16 = kk * 16;
            uint32_t af[2][4];
#pragma unroll
            for (int mt = 0; mt < 2; mt++) {
                uint32_t a = smem_u32(
                    &As[(m0 + mt * 16 + (lane & 15)) * AS_STRIDE + k16 + (lane >> 4) * 8]);
                ldsm_x4(af[mt][0], af[mt][1], af[mt][2], af[mt][3], a);
            }
            uint32_t bf[4][2];
#pragma unroll
            for (int nt2 = 0; nt2 < 2; nt2++) {
                uint32_t a = smem_u32(
                    &Bs[(k16 + (lane & 15)) * BS_STRIDE + n0 + nt2 * 16 + (lane >> 4) * 8]);
                uint32_t r0, r1, r2, r3;
                ldsm_x4_t(r0, r1, r2, r3, a);
                bf[nt2 * 2 + 0][0] = r0; bf[nt2 * 2 + 0][1] = r1;
                bf[nt2 * 2 + 1][0] = r2; bf[nt2 * 2 + 1][1] = r3;
            }
#pragma unroll
            for (int mt = 0; mt < 2; mt++)
#pragma unroll
                for (int nt = 0; nt < 4; nt++)
                    mma16816(acc[mt][nt], af[mt], bf[nt][0], bf[nt][1]);
        }
    }

    // Staged epilogue: scale rows by dinv, fp16 -> smem, coalesced stores.
    __syncthreads();
    int tg = lane >> 2, tp = lane & 3;
#pragma unroll
    for (int mt = 0; mt < 2; mt++) {
        int r0 = m0 + mt * 16 + tg;
        float dA = g_dinv[nb + r0];          // rows < MAXN by construction
        float dB = g_dinv[nb + r0 + 8];
#pragma unroll
        for (int nt = 0; nt < 4; nt++) {
            int col = n0 + nt * 8 + 2 * tp;
            __half2 hA = __floats2half2_rn(acc[mt][nt].x * dA, acc[mt][nt].y * dA);
            __half2 hB = __floats2half2_rn(acc[mt][nt].z * dB, acc[mt][nt].w * dB);
            *(__half2*)&Cs[r0 * CS_STRIDE + col] = hA;
            *(__half2*)&Cs[(r0 + 8) * CS_STRIDE + col] = hB;
        }
    }
    __syncthreads();
    // 64 rows x 16 uint4 = 1024 units; 4 per thread; coalesced global stores.
#pragma unroll
    for (int t = 0; t < 4; t++) {
        int i = tid + t * 256;
        int row = i >> 4, q = i & 15;
        int node = nb + row;
        if (node < N) {
            uint4 v = *(const uint4*)&Cs[row * CS_STRIDE + q * 8];
            *(uint4*)&g_h16[(size_t)node * HDIM + q * 8] = v;
        }
    }
}

// --- CSR aggregation: y[d] = relu(b + dinv[d]*(h'[d] + sum h'[src])) --------
// 4-edge unrolled gather (round-10 known-good config).
__global__ void __launch_bounds__(256)
agg16_kernel(const float* __restrict__ b, int N, int mode,
             const idx_t* __restrict__ batch, int G) {
    int n = blockIdx.x * 8 + (threadIdx.x >> 5);
    if (n >= N) return;
    int lane = threadIdx.x & 31;

    float4 acc = make_float4(0.f, 0.f, 0.f, 0.f);
    int e = g_off[n];
    int end = e + g_cnt[n];
    for (; e + 3 < end; e += 4) {
        int s0 = g_csr_src[e],     s1 = g_csr_src[e + 1];
        int s2 = g_csr_src[e + 2], s3 = g_csr_src[e + 3];
        uint2 u0 = *(const uint2*)&g_h16[(size_t)s0 * HDIM + lane * 4];
        uint2 u1 = *(const uint2*)&g_h16[(size_t)s1 * HDIM + lane * 4];
        uint2 u2 = *(const uint2*)&g_h16[(size_t)s2 * HDIM + lane * 4];
        uint2 u3 = *(const uint2*)&g_h16[(size_t)s3 * HDIM + lane * 4];
        float2 p0 = __half22float2(*(__half2*)&u0.x);
        float2 q0 = __half22float2(*(__half2*)&u0.y);
        float2 p1 = __half22float2(*(__half2*)&u1.x);
        float2 q1 = __half22float2(*(__half2*)&u1.y);
        float2 p2 = __half22float2(*(__half2*)&u2.x);
        float2 q2 = __half22float2(*(__half2*)&u2.y);
        float2 p3 = __half22float2(*(__half2*)&u3.x);
        float2 q3 = __half22float2(*(__half2*)&u3.y);
        acc.x += (p0.x + p1.x) + (p2.x + p3.x);
        acc.y += (p0.y + p1.y) + (p2.y + p3.y);
        acc.z += (q0.x + q1.x) + (q2.x + q3.x);
        acc.w += (q0.y + q1.y) + (q2.y + q3.y);
    }
    for (; e < end; e++) {
        int s0 = g_csr_src[e];
        uint2 u0 = *(const uint2*)&g_h16[(size_t)s0 * HDIM + lane * 4];
        float2 p0 = __half22float2(*(__half2*)&u0.x);
        float2 q0 = __half22float2(*(__half2*)&u0.y);
        acc.x += p0.x; acc.y += p0.y;
        acc.z += q0.x; acc.w += q0.y;
    }

    // Self term + bias + normalization + relu
    float di = g_dinv[n];
    float4 b4 = *(const float4*)&b[lane * 4];
    uint2 hs = *(const uint2*)&g_h16[(size_t)n * HDIM + lane * 4];
    float2 f0 = __half22float2(*(__half2*)&hs.x);
    float2 f1 = __half22float2(*(__half2*)&hs.y);
    acc.x = fmaxf(b4.x + di * (acc.x + f0.x), 0.f);
    acc.y = fmaxf(b4.y + di * (acc.y + f0.y), 0.f);
    acc.z = fmaxf(b4.z + di * (acc.z + f1.x), 0.f);
    acc.w = fmaxf(b4.w + di * (acc.w + f1.y), 0.f);

    if (mode == 0) {
        __half2 h01 = __floats2half2_rn(acc.x, acc.y);
        __half2 h23 = __floats2half2_rn(acc.z, acc.w);
        *(uint2*)&g_y16[(size_t)n * HDIM + lane * 4] =
            make_uint2(*(uint32_t*)&h01, *(uint32_t*)&h23);
    } else {
        int bg = (int)__ldg(&batch[n]);
        if ((unsigned)bg < (unsigned)G) {
            float* p = &g_gsum[bg * HDIM + lane * 4];
            asm volatile("red.global.add.v4.f32 [%0], {%1,%2,%3,%4};"
                         :: "l"(p), "f"(acc.x), "f"(acc.y), "f"(acc.z), "f"(acc.w)
                         : "memory");
            if (lane == 0) atomicAdd(&g_gcnt[bg], 1.0f);
        }
    }
}

// --- Final MLP: one block per graph ------------------------------------------
__global__ void __launch_bounds__(128)
mlp_kernel(const float* __restrict__ Wl1,
           const float* __restrict__ bl1,
           const float* __restrict__ Wl2,
           const float* __restrict__ bl2,
           float* __restrict__ out,
           int H2, int C) {
    __shared__ float xs[HDIM];
    __shared__ float h1[64];
    int g = blockIdx.x;
    int tid = threadIdx.x;

    float inv = 1.0f / fmaxf(g_gcnt[g], 1.0f);
    if (tid < HDIM) xs[tid] = g_gsum[g * HDIM + tid] * inv;
    __syncthreads();

    if (tid < H2) {
        float s = bl1[tid];
        for (int k = 0; k < HDIM; k++)
            s += xs[k] * Wl1[k * H2 + tid];
        h1[tid] = fmaxf(s, 0.f);
    }
    __syncthreads();

    if (tid < C) {
        float s = bl2[tid];
        for (int j = 0; j < H2; j++)
            s += h1[j] * Wl2[j * C + tid];
        out[g * C + tid] = s;
    }
}

// ---------------------------------------------------------------------------
extern "C" void kernel_launch(void* const* d_in, const int* in_sizes, int n_in,
                              void* d_out, int out_size) {
    const float* pos  = (const float*)d_in[0];
    const idx_t* ei   = (const idx_t*)d_in[1];
    const idx_t* batch= (const idx_t*)d_in[2];
    const float* W1   = (const float*)d_in[3];
    const float* b1   = (const float*)d_in[4];
    const float* W2   = (const float*)d_in[5];
    const float* b2   = (const float*)d_in[6];
    const float* W3   = (const float*)d_in[7];
    const float* b3   = (const float*)d_in[8];
    const float* Wl1  = (const float*)d_in[9];
    const float* bl1  = (const float*)d_in[10];
    const float* Wl2  = (const float*)d_in[11];
    const float* bl2  = (const float*)d_in[12];
    float* out = (float*)d_out;

    int H  = in_sizes[4];              // 128
    int D  = in_sizes[3] / H;          // 3
    int N  = in_sizes[0] / D;          // 50000
    int E  = in_sizes[1] / 2;          // 800000
    int H2 = in_sizes[10];             // 64
    int C  = in_sizes[12];             // 10
    int G  = out_size / C;             // 64

    int initN = N > G * H ? N : G * H;
    setup_kernel<<<(initN + 255) / 256, 256>>>(W2, W3, N, G * H, G);
    hist_kernel<<<(E + 255) / 256, 256>>>(ei, E, N);
    scan_kernel<<<(N + SCAN_CHUNK - 1) / SCAN_CHUNK, SCAN_THREADS>>>(pos, N);
    edge_fill<<<(E + 255) / 256, 256>>>(ei, E, N);

    // Layer 1 (fused: pos'-space aggregation + dense + relu)
    layer1_kernel<<<(N + 7) / 8, 256>>>(W1, b1, N);

    // Layer 2
    dense_mma_kernel<<<(N + 63) / 64, 256>>>(2, N);
    agg16_kernel<<<(N + 7) / 8, 256>>>(b2, N, 0, batch, G);

    // Layer 3 (aggregation fused with mean-pool)
    dense_mma_kernel<<<(N + 63) / 64, 256>>>(3, N);
    agg16_kernel<<<(N + 7) / 8, 256>>>(b3, N, 1, batch, G);

    mlp_kernel<<<G, 128>>>(Wl1, bl1, Wl2, bl2, out, H2, C);
}